// round 13
// baseline (speedup 1.0000x reference)
#include <cuda_runtime.h>
#include <cuda_fp16.h>
#include <math.h>

#define Nn   50000
#define Ee   100000
#define Bb   50
#define Mm   50
#define NPG  1000
#define EAe  98
#define WCOL 2688   /* 3*128 init + 18*128 root */
#define KRC  160    /* 159 padded to mult of 32 */

typedef unsigned long long ull;

// ---------------- scratch (__device__ globals) -----------------------------
__device__ __half g_Ah[54400000];        // [N,1088] fp16 (layer2); layer1 [N,544]
__device__ __half g_x16[Nn * 32];
__device__ __half g_h1h[Nn * 32];
__device__ float  g_h2[Nn * 64];
__device__ float  g_score[Nn];
__device__ float  g_agg1[Nn * 32];
__device__ float  g_agg2[Nn * 64];
__device__ __half g_haa16[Bb * Mm * KRC];
__device__ float  g_gout[3 * Bb * Mm * 128];
__device__ float  g_P[Mm * Mm];
__device__ __half g_Wt1h[32 * 544];
__device__ __half g_Wt2h[32 * 1088];
__device__ __half g_Wcat16[KRC * WCOL];
__device__ float  g_rc[2500 * WCOL];

// ---------------- f32x2 helpers (ARMA) --------------------------------------
__device__ __forceinline__ void ffma2(ull& d, ull a, ull b) {
    asm("fma.rn.f32x2 %0, %1, %2, %3;" : "=l"(d) : "l"(a), "l"(b), "l"(d));
}
__device__ __forceinline__ ull pack2(float lo, float hi) {
    ull r;
    asm("mov.b64 %0, {%1, %2};" : "=l"(r) : "r"(__float_as_uint(lo)), "r"(__float_as_uint(hi)));
    return r;
}
__device__ __forceinline__ void unpack2(ull v, float& lo, float& hi) {
    unsigned int a, b;
    asm("mov.b64 {%0, %1}, %2;" : "=r"(a), "=r"(b) : "l"(v));
    lo = __uint_as_float(a); hi = __uint_as_float(b);
}

// ------- fused prep: weight transposes + x16 + Wcat16 + zeros + P ----------
__global__ void k_prepF(const float* __restrict__ x,
                        const float* __restrict__ We1, const float* __restrict__ be1,
                        const float* __restrict__ We2, const float* __restrict__ be2,
                        const float* __restrict__ iw,  const float* __restrict__ rw,
                        const int* __restrict__ aei) {
    int stride = gridDim.x * blockDim.x;
    int t0 = blockIdx.x * blockDim.x + threadIdx.x;
    for (int i = t0; i < 32 * 544; i += stride) {
        int f = i / 544, r = i - f * 544;
        int d = r >> 5, o = r & 31;
        g_Wt1h[i] = __float2half((d < 16) ? We1[d * (32 * 32) + f * 32 + o] : be1[f * 32 + o]);
    }
    for (int i = t0; i < 32 * 1088; i += stride) {
        int f = i / 1088, r = i - f * 1088;
        int d = r >> 6, o = r & 63;
        g_Wt2h[i] = __float2half((d < 16) ? We2[d * (32 * 64) + f * 64 + o] : be2[f * 64 + o]);
    }
    for (int i = t0; i < Nn * 32; i += stride) g_x16[i] = __float2half(x[i]);
    for (int i = t0; i < KRC * WCOL; i += stride) {
        int f = i / WCOL, j = i - f * WCOL;
        float v = 0.f;
        if (f < 159) {
            if (j < 384) { int k = j >> 7, o = j & 127; v = iw[(k * 159 + f) * 128 + o]; }
            else { int tk = (j - 384) >> 7, o = (j - 384) & 127; v = rw[(tk * 159 + f) * 128 + o]; }
        }
        g_Wcat16[i] = __float2half(v);
    }
    for (int i = t0; i < Nn * 32; i += stride) g_agg1[i] = 0.f;
    for (int i = t0; i < Nn * 64; i += stride) g_agg2[i] = 0.f;

    // block 0: dense amino-graph propagation matrix
    if (blockIdx.x == 0) {
        __shared__ float deg[Mm];
        __shared__ float dinv[Mm];
        int tid = threadIdx.x;
        if (tid < Mm) deg[tid] = 0.f;
        __syncthreads();
        if (tid < EAe) atomicAdd(&deg[aei[EAe + tid]], 1.f);
        __syncthreads();
        if (tid < Mm) dinv[tid] = (deg[tid] > 0.f) ? rsqrtf(deg[tid]) : 0.f;
        for (int i = tid; i < Mm * Mm; i += blockDim.x) g_P[i] = 0.f;
        __syncthreads();
        if (tid < EAe) {
            int s = aei[tid], d = aei[EAe + tid];
            atomicAdd(&g_P[d * Mm + s], dinv[s] * dinv[d]);
        }
    }
}

// ------- B-resident tensor-core GEMM: C[M,N]=A[M,32]@B[32,N], fp16 out -----
__global__ __launch_bounds__(256) void k_mma_res(const __half* __restrict__ A,
                                                 const __half* __restrict__ B,
                                                 __half* __restrict__ C,
                                                 int M, int N, int npass, int sstride) {
    extern __shared__ __half sm[];
    __half* sB = sm;                      // 32 x sstride
    __half* sA = sm + 32 * sstride;       // 128 x 40
    int tid = threadIdx.x, lane = tid & 31, wid = tid >> 5;
    int bm = blockIdx.x * 128;
    int wm0 = (wid & 3) * 32, wn0 = (wid >> 2) * 32;
    const uint4 z4 = make_uint4(0, 0, 0, 0);

    int cap8 = npass * 8;
    for (int i = tid; i < 32 * cap8; i += 256) {
        int r = i / cap8, c8 = (i - r * cap8) * 8;
        uint4 v = z4;
        if (c8 < N) v = *(const uint4*)&B[(size_t)r * N + c8];
        *(uint4*)&sB[r * sstride + c8] = v;
    }
#pragma unroll
    for (int it = 0; it < 2; it++) {
        int c = tid + 256 * it;
        int r = c >> 2, cg = (c & 3) * 8;
        uint4 v = z4;
        int gr = bm + r;
        if (gr < M) v = *(const uint4*)&A[(size_t)gr * 32 + cg];
        *(uint4*)&sA[r * 40 + cg] = v;
    }
    __syncthreads();

    unsigned afr[2][2][4];
#pragma unroll
    for (int ks2 = 0; ks2 < 2; ks2++)
#pragma unroll
        for (int mi = 0; mi < 2; mi++) {
            int row = wm0 + mi * 16 + (lane & 7) + ((lane >> 3) & 1) * 8;
            unsigned addr = (unsigned)__cvta_generic_to_shared(
                &sA[row * 40 + ks2 * 16 + (lane >> 4) * 8]);
            asm volatile("ldmatrix.sync.aligned.m8n8.x4.shared.b16 {%0,%1,%2,%3}, [%4];"
                         : "=r"(afr[ks2][mi][0]), "=r"(afr[ks2][mi][1]),
                           "=r"(afr[ks2][mi][2]), "=r"(afr[ks2][mi][3])
                         : "r"(addr));
        }

    for (int np = 0; np < npass; np++) {
        int nb = np * 64;
        float acc[2][4][4];
#pragma unroll
        for (int mi = 0; mi < 2; mi++)
#pragma unroll
            for (int ni = 0; ni < 4; ni++)
#pragma unroll
                for (int q = 0; q < 4; q++) acc[mi][ni][q] = 0.f;

#pragma unroll
        for (int ks2 = 0; ks2 < 2; ks2++) {
            unsigned bf[4][2];
#pragma unroll
            for (int jb = 0; jb < 2; jb++) {
                int krow = ks2 * 16 + ((lane >> 3) & 1) * 8 + (lane & 7);
                int col  = nb + wn0 + jb * 16 + (lane >> 4) * 8;
                unsigned addr = (unsigned)__cvta_generic_to_shared(&sB[krow * sstride + col]);
                unsigned r0, r1, r2, r3;
                asm volatile("ldmatrix.sync.aligned.m8n8.x4.trans.shared.b16 {%0,%1,%2,%3}, [%4];"
                             : "=r"(r0), "=r"(r1), "=r"(r2), "=r"(r3) : "r"(addr));
                bf[2 * jb][0] = r0;     bf[2 * jb][1] = r1;
                bf[2 * jb + 1][0] = r2; bf[2 * jb + 1][1] = r3;
            }
#pragma unroll
            for (int mi = 0; mi < 2; mi++)
#pragma unroll
                for (int ni = 0; ni < 4; ni++) {
                    asm volatile(
                        "mma.sync.aligned.m16n8k16.row.col.f32.f16.f16.f32 "
                        "{%0,%1,%2,%3}, {%4,%5,%6,%7}, {%8,%9}, {%0,%1,%2,%3};"
                        : "+f"(acc[mi][ni][0]), "+f"(acc[mi][ni][1]),
                          "+f"(acc[mi][ni][2]), "+f"(acc[mi][ni][3])
                        : "r"(afr[ks2][mi][0]), "r"(afr[ks2][mi][1]),
                          "r"(afr[ks2][mi][2]), "r"(afr[ks2][mi][3]),
                          "r"(bf[ni][0]), "r"(bf[ni][1]));
                }
        }
#pragma unroll
        for (int mi = 0; mi < 2; mi++)
#pragma unroll
            for (int ni = 0; ni < 4; ni++) {
                int r0 = bm + wm0 + mi * 16 + (lane >> 2);
                int r1 = r0 + 8;
                int c  = nb + wn0 + ni * 8 + (lane & 3) * 2;
                if (c < N) {
                    if (r0 < M)
                        *(__half2*)&C[(size_t)r0 * N + c] =
                            __floats2half2_rn(acc[mi][ni][0], acc[mi][ni][1]);
                    if (r1 < M)
                        *(__half2*)&C[(size_t)r1 * N + c] =
                            __floats2half2_rn(acc[mi][ni][2], acc[mi][ni][3]);
                }
            }
    }
}

// ------- generic tensor-core GEMM (R5 geometry) for the rc GEMM ------------
__global__ __launch_bounds__(256) void k_mma(const __half* __restrict__ A,
                                             const __half* __restrict__ B,
                                             void* __restrict__ C,
                                             int M, int N, int K,
                                             int lda, int ldb, int ldc,
                                             int out_half) {
    __shared__ __half sA[128 * 40];
    __shared__ __half sB[32 * 72];
    int tid = threadIdx.x, lane = tid & 31, wid = tid >> 5;
    int bm = blockIdx.y * 128, bn = blockIdx.x * 64;
    int wm0 = (wid & 3) * 32, wn0 = (wid >> 2) * 32;

    float acc[2][4][4];
#pragma unroll
    for (int mi = 0; mi < 2; mi++)
#pragma unroll
        for (int ni = 0; ni < 4; ni++)
#pragma unroll
            for (int q = 0; q < 4; q++) acc[mi][ni][q] = 0.f;

    const uint4 z4 = make_uint4(0, 0, 0, 0);
    for (int k0 = 0; k0 < K; k0 += 32) {
#pragma unroll
        for (int it = 0; it < 2; it++) {
            int c = tid + 256 * it;
            int r = c >> 2, cg = (c & 3) * 8;
            uint4 v = z4;
            int gr = bm + r;
            if (gr < M) v = *(const uint4*)&A[(size_t)gr * lda + k0 + cg];
            *(uint4*)&sA[r * 40 + cg] = v;
        }
        {
            int r = tid >> 3, cg = (tid & 7) * 8;
            uint4 v = z4;
            int gc = bn + cg;
            if (gc < N) v = *(const uint4*)&B[(size_t)(k0 + r) * ldb + gc];
            *(uint4*)&sB[r * 72 + cg] = v;
        }
        __syncthreads();
#pragma unroll
        for (int ks = 0; ks < 32; ks += 16) {
            unsigned a[2][4];
#pragma unroll
            for (int mi = 0; mi < 2; mi++) {
                int row = wm0 + mi * 16 + (lane & 7) + ((lane >> 3) & 1) * 8;
                unsigned addr = (unsigned)__cvta_generic_to_shared(
                    &sA[row * 40 + ks + (lane >> 4) * 8]);
                asm volatile("ldmatrix.sync.aligned.m8n8.x4.shared.b16 {%0,%1,%2,%3}, [%4];"
                             : "=r"(a[mi][0]), "=r"(a[mi][1]), "=r"(a[mi][2]), "=r"(a[mi][3])
                             : "r"(addr));
            }
            unsigned bf[4][2];
#pragma unroll
            for (int jb = 0; jb < 2; jb++) {
                int krow = ks + ((lane >> 3) & 1) * 8 + (lane & 7);
                int col  = wn0 + jb * 16 + (lane >> 4) * 8;
                unsigned addr = (unsigned)__cvta_generic_to_shared(&sB[krow * 72 + col]);
                unsigned r0, r1, r2, r3;
                asm volatile("ldmatrix.sync.aligned.m8n8.x4.trans.shared.b16 {%0,%1,%2,%3}, [%4];"
                             : "=r"(r0), "=r"(r1), "=r"(r2), "=r"(r3) : "r"(addr));
                bf[2 * jb][0] = r0;     bf[2 * jb][1] = r1;
                bf[2 * jb + 1][0] = r2; bf[2 * jb + 1][1] = r3;
            }
#pragma unroll
            for (int mi = 0; mi < 2; mi++)
#pragma unroll
                for (int ni = 0; ni < 4; ni++) {
                    asm volatile(
                        "mma.sync.aligned.m16n8k16.row.col.f32.f16.f16.f32 "
                        "{%0,%1,%2,%3}, {%4,%5,%6,%7}, {%8,%9}, {%0,%1,%2,%3};"
                        : "+f"(acc[mi][ni][0]), "+f"(acc[mi][ni][1]),
                          "+f"(acc[mi][ni][2]), "+f"(acc[mi][ni][3])
                        : "r"(a[mi][0]), "r"(a[mi][1]), "r"(a[mi][2]), "r"(a[mi][3]),
                          "r"(bf[ni][0]), "r"(bf[ni][1]));
                }
        }
        __syncthreads();
    }
#pragma unroll
    for (int mi = 0; mi < 2; mi++)
#pragma unroll
        for (int ni = 0; ni < 4; ni++) {
            int r0 = bm + wm0 + mi * 16 + (lane >> 2);
            int r1 = r0 + 8;
            int c  = bn + wn0 + ni * 8 + (lane & 3) * 2;
            if (c < N) {
                if (out_half) {
                    __half* Ch = (__half*)C;
                    if (r0 < M)
                        *(__half2*)&Ch[(size_t)r0 * ldc + c] =
                            __floats2half2_rn(acc[mi][ni][0], acc[mi][ni][1]);
                    if (r1 < M)
                        *(__half2*)&Ch[(size_t)r1 * ldc + c] =
                            __floats2half2_rn(acc[mi][ni][2], acc[mi][ni][3]);
                } else {
                    float* Cf = (float*)C;
                    if (r0 < M) {
                        Cf[(size_t)r0 * ldc + c]     = acc[mi][ni][0];
                        Cf[(size_t)r0 * ldc + c + 1] = acc[mi][ni][1];
                    }
                    if (r1 < M) {
                        Cf[(size_t)r1 * ldc + c]     = acc[mi][ni][2];
                        Cf[(size_t)r1 * ldc + c + 1] = acc[mi][ni][3];
                    }
                }
            }
        }
}

// ------- edge message + scatter (warp per edge), fp16 A gather -------------
__global__ __launch_bounds__(256) void k_edge1(const float* __restrict__ ea, const int* __restrict__ eidx) {
    int w = (blockIdx.x * blockDim.x + threadIdx.x) >> 5;
    int lane = threadIdx.x & 31;
    if (w >= Ee) return;
    int s = eidx[w], d = eidx[Ee + w];
    float c = (lane < 16) ? ea[w * 16 + lane] : 1.f;
    const __half* Ar = g_Ah + (size_t)s * 544;
    float acc = 0.f;
#pragma unroll
    for (int dd = 0; dd < 17; dd++) {
        float cd = __shfl_sync(0xffffffffu, c, dd);
        acc += cd * __half2float(Ar[dd * 32 + lane]);
    }
    atomicAdd(&g_agg1[d * 32 + lane], acc);
}

__global__ __launch_bounds__(256) void k_edge2(const float* __restrict__ ea, const int* __restrict__ eidx) {
    int w = (blockIdx.x * blockDim.x + threadIdx.x) >> 5;
    int lane = threadIdx.x & 31;
    if (w >= Ee) return;
    int s = eidx[w], d = eidx[Ee + w];
    float c = (lane < 16) ? ea[w * 16 + lane] : 1.f;
    const __half* Ar = g_Ah + (size_t)s * 1088;
    float a0 = 0.f, a1 = 0.f;
#pragma unroll
    for (int dd = 0; dd < 17; dd++) {
        float cd = __shfl_sync(0xffffffffu, c, dd);
        __half2 h2 = *(const __half2*)&Ar[dd * 64 + 2 * lane];
        float2 f2 = __half22float2(h2);
        a0 += cd * f2.x;
        a1 += cd * f2.y;
    }
    atomicAdd(&g_agg2[d * 64 + 2 * lane],     a0);
    atomicAdd(&g_agg2[d * 64 + 2 * lane + 1], a1);
}

// ------- node updates ------------------------------------------------------
__global__ __launch_bounds__(256) void k_update1(const float* __restrict__ x,
                                                 const float* __restrict__ root,
                                                 const float* __restrict__ bias) {
    int w = (blockIdx.x * blockDim.x + threadIdx.x) >> 5;
    int lane = threadIdx.x & 31;
    if (w >= Nn) return;
    float xv = x[w * 32 + lane];
    float acc = g_agg1[w * 32 + lane] + bias[lane];
#pragma unroll
    for (int f = 0; f < 32; f++)
        acc += __shfl_sync(0xffffffffu, xv, f) * root[f * 32 + lane];
    g_h1h[w * 32 + lane] = __float2half(fmaxf(acc, 0.f));
}

// update2 + fused attention score (h2 is in registers; avoid readout re-read)
__global__ __launch_bounds__(256) void k_update2(const float* __restrict__ root,
                                                 const float* __restrict__ bias,
                                                 const float* __restrict__ Wa,
                                                 const float* __restrict__ ba) {
    int w = (blockIdx.x * blockDim.x + threadIdx.x) >> 5;
    int lane = threadIdx.x & 31;
    if (w >= Nn) return;
    float hv = __half2float(g_h1h[w * 32 + lane]);
    float a0 = g_agg2[w * 64 + lane] + bias[lane];
    float a1 = g_agg2[w * 64 + 32 + lane] + bias[32 + lane];
#pragma unroll
    for (int f = 0; f < 32; f++) {
        float hs = __shfl_sync(0xffffffffu, hv, f);
        a0 += hs * root[f * 64 + lane];
        a1 += hs * root[f * 64 + 32 + lane];
    }
    a0 = fmaxf(a0, 0.f);
    a1 = fmaxf(a1, 0.f);
    g_h2[w * 64 + lane] = a0;
    g_h2[w * 64 + 32 + lane] = a1;
    float sc = a0 * Wa[lane] + a1 * Wa[32 + lane];
#pragma unroll
    for (int o = 16; o; o >>= 1) sc += __shfl_xor_sync(0xffffffffu, sc, o);
    if (lane == 0) g_score[w] = sc + ba[0];
}

// ------- per-graph attention readout (scores precomputed) -> haa16 ---------
__global__ __launch_bounds__(256) void k_readout(const float* __restrict__ aaf,
                                                 const int* __restrict__ lbl) {
    __shared__ float ssc[NPG];
    __shared__ float red[8];
    __shared__ float saa[Mm * 64];
    int b = blockIdx.x, tid = threadIdx.x;
    int wid = tid >> 5, lane = tid & 31;
    for (int i = tid; i < Mm * 64; i += 256) saa[i] = 0.f;
    const float* h = g_h2 + (size_t)b * NPG * 64;
    float lmax = -1e30f;
    for (int i = tid; i < NPG; i += 256) {
        float s = g_score[b * NPG + i];
        ssc[i] = s;
        lmax = fmaxf(lmax, s);
    }
#pragma unroll
    for (int o = 16; o; o >>= 1) lmax = fmaxf(lmax, __shfl_xor_sync(0xffffffffu, lmax, o));
    if (lane == 0) red[wid] = lmax;
    __syncthreads();
    float gmax = red[0];
#pragma unroll
    for (int i = 1; i < 8; i++) gmax = fmaxf(gmax, red[i]);
    float lsum = 0.f;
    for (int i = tid; i < NPG; i += 256) {
        float e = __expf(ssc[i] - gmax);
        ssc[i] = e;
        lsum += e;
    }
#pragma unroll
    for (int o = 16; o; o >>= 1) lsum += __shfl_xor_sync(0xffffffffu, lsum, o);
    __syncthreads();
    if (lane == 0) red[wid] = lsum;
    __syncthreads();
    float gsum = 0.f;
#pragma unroll
    for (int i = 0; i < 8; i++) gsum += red[i];
    float inv = 1.f / gsum;
    for (int i = wid; i < NPG; i += 8) {
        float a = ssc[i] * inv;
        int m = lbl[b * NPG + i];
        atomicAdd(&saa[m * 64 + lane], h[i * 64 + lane] * a);
        atomicAdd(&saa[m * 64 + 32 + lane], h[i * 64 + 32 + lane] * a);
    }
    __syncthreads();
    for (int i = tid; i < Mm * KRC; i += 256) {
        int m = i / KRC, f = i - m * KRC;
        float v = 0.f;
        if (f < 64) v = saa[m * 64 + f];
        else if (f < 159) v = aaf[(b * Mm + m) * 95 + (f - 64)];
        g_haa16[(b * Mm + m) * KRC + f] = __float2half(v);
    }
}

// ------- ARMA recurrence; rootc precomputed in g_rc ------------------------
#define ARMA_SP   0
#define ARMA_SB   2800
#define ARMA_SB2  (2800 + 7168)
#define ARMA_SW   (2800 + 7168 + 7168)
#define ARMA_SMEM ((2800 + 7168 + 7168 + 16384) * 4)

__device__ __forceinline__ void arma_acc2(const float* __restrict__ Am, int lda,
                                          const float* __restrict__ Bm, int inner,
                                          ull acc[7][2], int ty, int tx) {
    for (int i = 0; i < inner; i++) {
        ull bb0 = *(const ull*)&Bm[i * 128 + 2 * tx];
        ull bb1 = *(const ull*)&Bm[i * 128 + 64 + 2 * tx];
#pragma unroll
        for (int rr = 0; rr < 7; rr++) {
            float a = Am[(ty * 7 + rr) * lda + i];
            ull aa = pack2(a, a);
            ffma2(acc[rr][0], aa, bb0);
            ffma2(acc[rr][1], aa, bb1);
        }
    }
}

__global__ __launch_bounds__(256) void k_arma2(const float* __restrict__ aw,
                                               const float* __restrict__ ab) {
    extern __shared__ float dyn[];
    float* sP  = dyn + ARMA_SP;
    float* sB  = dyn + ARMA_SB;
    float* sB2 = dyn + ARMA_SB2;
    float* sW  = dyn + ARMA_SW;
    int b = blockIdx.x / 3, k = blockIdx.x % 3;
    int tid = threadIdx.x, ty = tid >> 5, tx = tid & 31;

    for (int i = tid; i < 2800; i += 256) sP[i] = (i < 2500) ? g_P[i] : 0.f;
    for (int i = tid; i < 56 * 128; i += 256) {
        int r = i >> 7, c = i & 127;
        sB[i]  = (r < 50) ? g_rc[(size_t)(b * 50 + r) * WCOL + k * 128 + c] : 0.f;
        sB2[i] = 0.f;
    }
    __syncthreads();

    ull acc[7][2];
    for (int t = 0; t < 6; t++) {
        const float* cur = sB;
        if (t > 0) {
            const float* W = aw + (size_t)((t - 1) * 3 + k) * 16384;
            for (int i = tid * 4; i < 16384; i += 1024)
                *(float4*)&sW[i] = *(const float4*)&W[i];
            __syncthreads();
#pragma unroll
            for (int rr = 0; rr < 7; rr++) { acc[rr][0] = 0ull; acc[rr][1] = 0ull; }
            arma_acc2(sB, 128, sW, 128, acc, ty, tx);
            __syncthreads();
#pragma unroll
            for (int rr = 0; rr < 7; rr++) {
                int r = ty * 7 + rr;
                if (r < Mm) {
                    float l0, h0, l1, h1;
                    unpack2(acc[rr][0], l0, h0);
                    unpack2(acc[rr][1], l1, h1);
                    sB2[r * 128 + 2 * tx]      = l0;
                    sB2[r * 128 + 2 * tx + 1]  = h0;
                    sB2[r * 128 + 64 + 2 * tx] = l1;
                    sB2[r * 128 + 65 + 2 * tx] = h1;
                }
            }
            __syncthreads();
            cur = sB2;
        }
#pragma unroll
        for (int rr = 0; rr < 7; rr++) { acc[rr][0] = 0ull; acc[rr][1] = 0ull; }
        arma_acc2(sP, 50, cur, 50, acc, ty, tx);
        const float* bias = ab + (t * 3 + k) * 128;
        float bl0 = bias[2 * tx], bh0 = bias[2 * tx + 1];
        float bl1 = bias[64 + 2 * tx], bh1 = bias[65 + 2 * tx];
        __syncthreads();
#pragma unroll
        for (int rr = 0; rr < 7; rr++) {
            int r = ty * 7 + rr;
            if (r < Mm) {
                const float* rc = &g_rc[(size_t)(b * 50 + r) * WCOL + 384 + (t * 3 + k) * 128];
                float l0, h0, l1, h1;
                unpack2(acc[rr][0], l0, h0);
                unpack2(acc[rr][1], l1, h1);
                sB[r * 128 + 2 * tx]      = fmaxf(l0 + rc[2 * tx]      + bl0, 0.f);
                sB[r * 128 + 2 * tx + 1]  = fmaxf(h0 + rc[2 * tx + 1]  + bh0, 0.f);
                sB[r * 128 + 64 + 2 * tx] = fmaxf(l1 + rc[64 + 2 * tx] + bl1, 0.f);
                sB[r * 128 + 65 + 2 * tx] = fmaxf(h1 + rc[65 + 2 * tx] + bh1, 0.f);
            }
        }
        __syncthreads();
    }
    float* dst = g_gout + (size_t)(k * Bb + b) * Mm * 128;
    for (int i = tid; i < Mm * 128; i += 256) dst[i] = sB[i];
}

// ------- amino attention + MLP head ----------------------------------------
__global__ __launch_bounds__(128) void k_head(const float* __restrict__ Waa, const float* __restrict__ baa,
                                              const float* __restrict__ W1, const float* __restrict__ b1,
                                              const float* __restrict__ W2, const float* __restrict__ b2,
                                              const float* __restrict__ W3, const float* __restrict__ b3,
                                              const float* __restrict__ W4, const float* __restrict__ b4,
                                              float* __restrict__ out) {
    __shared__ float gv[Mm * 128];
    __shared__ float s[Mm];
    __shared__ float p[128];
    __shared__ float h1[64], h2s[32], h3[16];
    int b = blockIdx.x, tid = threadIdx.x;
    for (int i = tid; i < Mm * 128; i += 128)
        gv[i] = (g_gout[(size_t)(0 * Bb + b) * Mm * 128 + i] +
                 g_gout[(size_t)(1 * Bb + b) * Mm * 128 + i] +
                 g_gout[(size_t)(2 * Bb + b) * Mm * 128 + i]) * (1.f / 3.f);
    __syncthreads();
    if (tid < Mm) {
        float sc = baa[0];
#pragma unroll 8
        for (int c = 0; c < 128; c++) sc += gv[tid * 128 + c] * Waa[c];
        s[tid] = sc;
    }
    __syncthreads();
    if (tid == 0) {
        float mx = -1e30f;
        for (int m = 0; m < Mm; m++) mx = fmaxf(mx, s[m]);
        float sum = 0.f;
        for (int m = 0; m < Mm; m++) { s[m] = __expf(s[m] - mx); sum += s[m]; }
        float inv = 1.f / sum;
        for (int m = 0; m < Mm; m++) s[m] *= inv;
    }
    __syncthreads();
    {
        float acc = 0.f;
        for (int m = 0; m < Mm; m++) acc += gv[m * 128 + tid] * s[m];
        p[tid] = acc;
    }
    __syncthreads();
    if (tid < 64) {
        float a = b1[tid];
        for (int c = 0; c < 128; c++) a += p[c] * W1[c * 64 + tid];
        h1[tid] = fmaxf(a, 0.f);
    }
    __syncthreads();
    if (tid < 32) {
        float a = b2[tid];
        for (int c = 0; c < 64; c++) a += h1[c] * W2[c * 32 + tid];
        h2s[tid] = fmaxf(a, 0.f);
    }
    __syncthreads();
    if (tid < 16) {
        float a = b3[tid];
        for (int c = 0; c < 32; c++) a += h2s[c] * W3[c * 16 + tid];
        h3[tid] = fmaxf(a, 0.f);
    }
    __syncthreads();
    if (tid == 0) {
        float a = b4[0];
        for (int c = 0; c < 16; c++) a += h3[c] * W4[c];
        out[b] = a;
    }
}

// ---------------------------------------------------------------------------
extern "C" void kernel_launch(void* const* d_in, const int* in_sizes, int n_in,
                              void* d_out, int out_size) {
    const float* x        = (const float*)d_in[0];
    const float* ea       = (const float*)d_in[1];
    const float* aaf      = (const float*)d_in[2];
    const int*   eidx     = (const int*)d_in[3];
    const int*   lbl      = (const int*)d_in[4];
    const int*   aei      = (const int*)d_in[5];
    const float* We1      = (const float*)d_in[6];
    const float* be1      = (const float*)d_in[7];
    const float* root1    = (const float*)d_in[8];
    const float* bias1    = (const float*)d_in[9];
    const float* We2      = (const float*)d_in[10];
    const float* be2      = (const float*)d_in[11];
    const float* root2    = (const float*)d_in[12];
    const float* bias2    = (const float*)d_in[13];
    const float* WaAtom   = (const float*)d_in[14];
    const float* baAtom   = (const float*)d_in[15];
    const float* armaInit = (const float*)d_in[16];
    const float* armaW    = (const float*)d_in[17];
    const float* armaRoot = (const float*)d_in[18];
    const float* armaBias = (const float*)d_in[19];
    const float* WaAa     = (const float*)d_in[20];
    const float* baAa     = (const float*)d_in[21];
    const float* W1 = (const float*)d_in[22]; const float* b1 = (const float*)d_in[23];
    const float* W2 = (const float*)d_in[24]; const float* b2 = (const float*)d_in[25];
    const float* W3 = (const float*)d_in[26]; const float* b3 = (const float*)d_in[27];
    const float* W4 = (const float*)d_in[28]; const float* b4 = (const float*)d_in[29];
    float* out = (float*)d_out;

    void *pAh, *pX16, *pH1h, *pWt1h, *pWt2h, *pHaa16, *pWcat16;
    float* pRc;
    cudaGetSymbolAddress(&pAh,     g_Ah);
    cudaGetSymbolAddress(&pX16,    g_x16);
    cudaGetSymbolAddress(&pH1h,    g_h1h);
    cudaGetSymbolAddress(&pWt1h,   g_Wt1h);
    cudaGetSymbolAddress(&pWt2h,   g_Wt2h);
    cudaGetSymbolAddress(&pHaa16,  g_haa16);
    cudaGetSymbolAddress(&pWcat16, g_Wcat16);
    cudaGetSymbolAddress((void**)&pRc, g_rc);
    cudaFuncSetAttribute(k_arma2, cudaFuncAttributeMaxDynamicSharedMemorySize, ARMA_SMEM);
    cudaFuncSetAttribute(k_mma_res, cudaFuncAttributeMaxDynamicSharedMemorySize, 81000);

    // #1 fused prep (weights + x16 + Wcat + zeros + P)
    k_prepF<<<1024, 256>>>(x, We1, be1, We2, be2, armaInit, armaRoot, aei);
    // #2 layer1 GEMM (B-resident)
    k_mma_res<<<391, 256, 47616>>>((const __half*)pX16, (const __half*)pWt1h,
                                   (__half*)pAh, Nn, 544, 9, 584);
    // #3 edge1
    k_edge1<<<12500, 256>>>(ea, eidx);
    // #4 update1  <- profiled slot
    k_update1<<<6250, 256>>>(x, root1, bias1);
    // #5 layer2 GEMM (B-resident)
    k_mma_res<<<391, 256, 80384>>>((const __half*)pH1h, (const __half*)pWt2h,
                                   (__half*)pAh, Nn, 1088, 17, 1096);
    // #6-#7 edge2 + update2(+score)
    k_edge2<<<12500, 256>>>(ea, eidx);
    k_update2<<<6250, 256>>>(root2, bias2, WaAtom, baAtom);
    // #8 readout (uses precomputed scores)
    k_readout<<<Bb, 256>>>(aaf, lbl);
    // #9 rc GEMM
    k_mma<<<dim3(42, 20), 256>>>((const __half*)pHaa16, (const __half*)pWcat16, pRc,
                                 Bb * Mm, WCOL, KRC, KRC, WCOL, WCOL, 0);
    // #10-#11 ARMA + head
    k_arma2<<<3 * Bb, 256, ARMA_SMEM>>>(armaW, armaBias);
    k_head<<<Bb, 128>>>(WaAa, baAa, W1, b1, W2, b2, W3, b3, W4, b4, out);
}

// round 14
// speedup vs baseline: 1.4648x; 1.4648x over previous
#include <cuda_runtime.h>
#include <cuda_fp16.h>
#include <math.h>

#define Nn   50000
#define Ee   100000
#define Bb   50
#define Mm   50
#define NPG  1000
#define EAe  98
#define WCOL 2688   /* 3*128 init + 18*128 root */
#define KRC  160    /* 159 padded to mult of 32 */
#define W1C  576    /* 544 edge-cols + 32 root1 cols */
#define W2C  1152   /* 1088 edge-cols + 64 root2 cols */

typedef unsigned long long ull;

// ---------------- scratch (__device__ globals) -----------------------------
__device__ __half g_Ah[57600000];        // [N,1152] fp16 (layer2); layer1 [N,576]
__device__ __half g_x16[Nn * 32];
__device__ __half g_h1h[Nn * 32];
__device__ float  g_h2[Nn * 64];
__device__ float  g_score[Nn];
__device__ float  g_agg1[Nn * 32];
__device__ float  g_agg2[Nn * 64];
__device__ __half g_haa16[Bb * Mm * KRC];
__device__ float  g_gout[3 * Bb * Mm * 128];
__device__ float  g_P[Mm * Mm];
__device__ __half g_Wt1h[32 * W1C];
__device__ __half g_Wt2h[32 * W2C];
__device__ __half g_Wcat16[KRC * WCOL];
__device__ float  g_rc[2500 * WCOL];

// ---------------- f32x2 helpers (ARMA) --------------------------------------
__device__ __forceinline__ void ffma2(ull& d, ull a, ull b) {
    asm("fma.rn.f32x2 %0, %1, %2, %3;" : "=l"(d) : "l"(a), "l"(b), "l"(d));
}
__device__ __forceinline__ ull pack2(float lo, float hi) {
    ull r;
    asm("mov.b64 %0, {%1, %2};" : "=l"(r) : "r"(__float_as_uint(lo)), "r"(__float_as_uint(hi)));
    return r;
}
__device__ __forceinline__ void unpack2(ull v, float& lo, float& hi) {
    unsigned int a, b;
    asm("mov.b64 {%0, %1}, %2;" : "=r"(a), "=r"(b) : "l"(v));
    lo = __uint_as_float(a); hi = __uint_as_float(b);
}

// ------- fused prep: weights(+root cols) + x16 + Wcat16 + zeros + P --------
__global__ void k_prepF(const float* __restrict__ x,
                        const float* __restrict__ We1, const float* __restrict__ be1,
                        const float* __restrict__ root1,
                        const float* __restrict__ We2, const float* __restrict__ be2,
                        const float* __restrict__ root2,
                        const float* __restrict__ iw,  const float* __restrict__ rw,
                        const int* __restrict__ aei) {
    int stride = gridDim.x * blockDim.x;
    int t0 = blockIdx.x * blockDim.x + threadIdx.x;
    // Wt1 [32 x 576]: cols 0..543 edge-MLP (bias folded d=16), 544..575 root1
    for (int i = t0; i < 32 * W1C; i += stride) {
        int f = i / W1C, r = i - f * W1C;
        float v;
        if (r < 544) {
            int d = r >> 5, o = r & 31;
            v = (d < 16) ? We1[d * (32 * 32) + f * 32 + o] : be1[f * 32 + o];
        } else v = root1[f * 32 + (r - 544)];
        g_Wt1h[i] = __float2half(v);
    }
    // Wt2 [32 x 1152]: cols 0..1087 edge-MLP, 1088..1151 root2
    for (int i = t0; i < 32 * W2C; i += stride) {
        int f = i / W2C, r = i - f * W2C;
        float v;
        if (r < 1088) {
            int d = r >> 6, o = r & 63;
            v = (d < 16) ? We2[d * (32 * 64) + f * 64 + o] : be2[f * 64 + o];
        } else v = root2[f * 64 + (r - 1088)];
        g_Wt2h[i] = __float2half(v);
    }
    for (int i = t0; i < Nn * 32; i += stride) g_x16[i] = __float2half(x[i]);
    for (int i = t0; i < KRC * WCOL; i += stride) {
        int f = i / WCOL, j = i - f * WCOL;
        float v = 0.f;
        if (f < 159) {
            if (j < 384) { int k = j >> 7, o = j & 127; v = iw[(k * 159 + f) * 128 + o]; }
            else { int tk = (j - 384) >> 7, o = (j - 384) & 127; v = rw[(tk * 159 + f) * 128 + o]; }
        }
        g_Wcat16[i] = __float2half(v);
    }
    for (int i = t0; i < Nn * 32; i += stride) g_agg1[i] = 0.f;
    for (int i = t0; i < Nn * 64; i += stride) g_agg2[i] = 0.f;

    if (blockIdx.x == 0) {
        __shared__ float deg[Mm];
        __shared__ float dinv[Mm];
        int tid = threadIdx.x;
        if (tid < Mm) deg[tid] = 0.f;
        __syncthreads();
        if (tid < EAe) atomicAdd(&deg[aei[EAe + tid]], 1.f);
        __syncthreads();
        if (tid < Mm) dinv[tid] = (deg[tid] > 0.f) ? rsqrtf(deg[tid]) : 0.f;
        for (int i = tid; i < Mm * Mm; i += blockDim.x) g_P[i] = 0.f;
        __syncthreads();
        if (tid < EAe) {
            int s = aei[tid], d = aei[EAe + tid];
            atomicAdd(&g_P[d * Mm + s], dinv[s] * dinv[d]);
        }
    }
}

// ------- B-resident tensor-core GEMM: C[M,N]=A[M,32]@B[32,N], fp16 out -----
__global__ __launch_bounds__(256) void k_mma_res(const __half* __restrict__ A,
                                                 const __half* __restrict__ B,
                                                 __half* __restrict__ C,
                                                 int M, int N, int npass, int sstride) {
    extern __shared__ __half sm[];
    __half* sB = sm;                      // 32 x sstride
    __half* sA = sm + 32 * sstride;       // 128 x 40
    int tid = threadIdx.x, lane = tid & 31, wid = tid >> 5;
    int bm = blockIdx.x * 128;
    int wm0 = (wid & 3) * 32, wn0 = (wid >> 2) * 32;
    const uint4 z4 = make_uint4(0, 0, 0, 0);

    int cap8 = npass * 8;
    for (int i = tid; i < 32 * cap8; i += 256) {
        int r = i / cap8, c8 = (i - r * cap8) * 8;
        uint4 v = z4;
        if (c8 < N) v = *(const uint4*)&B[(size_t)r * N + c8];
        *(uint4*)&sB[r * sstride + c8] = v;
    }
#pragma unroll
    for (int it = 0; it < 2; it++) {
        int c = tid + 256 * it;
        int r = c >> 2, cg = (c & 3) * 8;
        uint4 v = z4;
        int gr = bm + r;
        if (gr < M) v = *(const uint4*)&A[(size_t)gr * 32 + cg];
        *(uint4*)&sA[r * 40 + cg] = v;
    }
    __syncthreads();

    unsigned afr[2][2][4];
#pragma unroll
    for (int ks2 = 0; ks2 < 2; ks2++)
#pragma unroll
        for (int mi = 0; mi < 2; mi++) {
            int row = wm0 + mi * 16 + (lane & 7) + ((lane >> 3) & 1) * 8;
            unsigned addr = (unsigned)__cvta_generic_to_shared(
                &sA[row * 40 + ks2 * 16 + (lane >> 4) * 8]);
            asm volatile("ldmatrix.sync.aligned.m8n8.x4.shared.b16 {%0,%1,%2,%3}, [%4];"
                         : "=r"(afr[ks2][mi][0]), "=r"(afr[ks2][mi][1]),
                           "=r"(afr[ks2][mi][2]), "=r"(afr[ks2][mi][3])
                         : "r"(addr));
        }

    for (int np = 0; np < npass; np++) {
        int nb = np * 64;
        float acc[2][4][4];
#pragma unroll
        for (int mi = 0; mi < 2; mi++)
#pragma unroll
            for (int ni = 0; ni < 4; ni++)
#pragma unroll
                for (int q = 0; q < 4; q++) acc[mi][ni][q] = 0.f;

#pragma unroll
        for (int ks2 = 0; ks2 < 2; ks2++) {
            unsigned bf[4][2];
#pragma unroll
            for (int jb = 0; jb < 2; jb++) {
                int krow = ks2 * 16 + ((lane >> 3) & 1) * 8 + (lane & 7);
                int col  = nb + wn0 + jb * 16 + (lane >> 4) * 8;
                unsigned addr = (unsigned)__cvta_generic_to_shared(&sB[krow * sstride + col]);
                unsigned r0, r1, r2, r3;
                asm volatile("ldmatrix.sync.aligned.m8n8.x4.trans.shared.b16 {%0,%1,%2,%3}, [%4];"
                             : "=r"(r0), "=r"(r1), "=r"(r2), "=r"(r3) : "r"(addr));
                bf[2 * jb][0] = r0;     bf[2 * jb][1] = r1;
                bf[2 * jb + 1][0] = r2; bf[2 * jb + 1][1] = r3;
            }
#pragma unroll
            for (int mi = 0; mi < 2; mi++)
#pragma unroll
                for (int ni = 0; ni < 4; ni++) {
                    asm volatile(
                        "mma.sync.aligned.m16n8k16.row.col.f32.f16.f16.f32 "
                        "{%0,%1,%2,%3}, {%4,%5,%6,%7}, {%8,%9}, {%0,%1,%2,%3};"
                        : "+f"(acc[mi][ni][0]), "+f"(acc[mi][ni][1]),
                          "+f"(acc[mi][ni][2]), "+f"(acc[mi][ni][3])
                        : "r"(afr[ks2][mi][0]), "r"(afr[ks2][mi][1]),
                          "r"(afr[ks2][mi][2]), "r"(afr[ks2][mi][3]),
                          "r"(bf[ni][0]), "r"(bf[ni][1]));
                }
        }
#pragma unroll
        for (int mi = 0; mi < 2; mi++)
#pragma unroll
            for (int ni = 0; ni < 4; ni++) {
                int r0 = bm + wm0 + mi * 16 + (lane >> 2);
                int r1 = r0 + 8;
                int c  = nb + wn0 + ni * 8 + (lane & 3) * 2;
                if (c < N) {
                    if (r0 < M)
                        *(__half2*)&C[(size_t)r0 * N + c] =
                            __floats2half2_rn(acc[mi][ni][0], acc[mi][ni][1]);
                    if (r1 < M)
                        *(__half2*)&C[(size_t)r1 * N + c] =
                            __floats2half2_rn(acc[mi][ni][2], acc[mi][ni][3]);
                }
            }
    }
}

// ------- generic tensor-core GEMM (R5 geometry) for the rc GEMM ------------
__global__ __launch_bounds__(256) void k_mma(const __half* __restrict__ A,
                                             const __half* __restrict__ B,
                                             void* __restrict__ C,
                                             int M, int N, int K,
                                             int lda, int ldb, int ldc,
                                             int out_half) {
    __shared__ __half sA[128 * 40];
    __shared__ __half sB[32 * 72];
    int tid = threadIdx.x, lane = tid & 31, wid = tid >> 5;
    int bm = blockIdx.y * 128, bn = blockIdx.x * 64;
    int wm0 = (wid & 3) * 32, wn0 = (wid >> 2) * 32;

    float acc[2][4][4];
#pragma unroll
    for (int mi = 0; mi < 2; mi++)
#pragma unroll
        for (int ni = 0; ni < 4; ni++)
#pragma unroll
            for (int q = 0; q < 4; q++) acc[mi][ni][q] = 0.f;

    const uint4 z4 = make_uint4(0, 0, 0, 0);
    for (int k0 = 0; k0 < K; k0 += 32) {
#pragma unroll
        for (int it = 0; it < 2; it++) {
            int c = tid + 256 * it;
            int r = c >> 2, cg = (c & 3) * 8;
            uint4 v = z4;
            int gr = bm + r;
            if (gr < M) v = *(const uint4*)&A[(size_t)gr * lda + k0 + cg];
            *(uint4*)&sA[r * 40 + cg] = v;
        }
        {
            int r = tid >> 3, cg = (tid & 7) * 8;
            uint4 v = z4;
            int gc = bn + cg;
            if (gc < N) v = *(const uint4*)&B[(size_t)(k0 + r) * ldb + gc];
            *(uint4*)&sB[r * 72 + cg] = v;
        }
        __syncthreads();
#pragma unroll
        for (int ks = 0; ks < 32; ks += 16) {
            unsigned a[2][4];
#pragma unroll
            for (int mi = 0; mi < 2; mi++) {
                int row = wm0 + mi * 16 + (lane & 7) + ((lane >> 3) & 1) * 8;
                unsigned addr = (unsigned)__cvta_generic_to_shared(
                    &sA[row * 40 + ks + (lane >> 4) * 8]);
                asm volatile("ldmatrix.sync.aligned.m8n8.x4.shared.b16 {%0,%1,%2,%3}, [%4];"
                             : "=r"(a[mi][0]), "=r"(a[mi][1]), "=r"(a[mi][2]), "=r"(a[mi][3])
                             : "r"(addr));
            }
            unsigned bf[4][2];
#pragma unroll
            for (int jb = 0; jb < 2; jb++) {
                int krow = ks + ((lane >> 3) & 1) * 8 + (lane & 7);
                int col  = wn0 + jb * 16 + (lane >> 4) * 8;
                unsigned addr = (unsigned)__cvta_generic_to_shared(&sB[krow * 72 + col]);
                unsigned r0, r1, r2, r3;
                asm volatile("ldmatrix.sync.aligned.m8n8.x4.trans.shared.b16 {%0,%1,%2,%3}, [%4];"
                             : "=r"(r0), "=r"(r1), "=r"(r2), "=r"(r3) : "r"(addr));
                bf[2 * jb][0] = r0;     bf[2 * jb][1] = r1;
                bf[2 * jb + 1][0] = r2; bf[2 * jb + 1][1] = r3;
            }
#pragma unroll
            for (int mi = 0; mi < 2; mi++)
#pragma unroll
                for (int ni = 0; ni < 4; ni++) {
                    asm volatile(
                        "mma.sync.aligned.m16n8k16.row.col.f32.f16.f16.f32 "
                        "{%0,%1,%2,%3}, {%4,%5,%6,%7}, {%8,%9}, {%0,%1,%2,%3};"
                        : "+f"(acc[mi][ni][0]), "+f"(acc[mi][ni][1]),
                          "+f"(acc[mi][ni][2]), "+f"(acc[mi][ni][3])
                        : "r"(a[mi][0]), "r"(a[mi][1]), "r"(a[mi][2]), "r"(a[mi][3]),
                          "r"(bf[ni][0]), "r"(bf[ni][1]));
                }
        }
        __syncthreads();
    }
#pragma unroll
    for (int mi = 0; mi < 2; mi++)
#pragma unroll
        for (int ni = 0; ni < 4; ni++) {
            int r0 = bm + wm0 + mi * 16 + (lane >> 2);
            int r1 = r0 + 8;
            int c  = bn + wn0 + ni * 8 + (lane & 3) * 2;
            if (c < N) {
                if (out_half) {
                    __half* Ch = (__half*)C;
                    if (r0 < M)
                        *(__half2*)&Ch[(size_t)r0 * ldc + c] =
                            __floats2half2_rn(acc[mi][ni][0], acc[mi][ni][1]);
                    if (r1 < M)
                        *(__half2*)&Ch[(size_t)r1 * ldc + c] =
                            __floats2half2_rn(acc[mi][ni][2], acc[mi][ni][3]);
                } else {
                    float* Cf = (float*)C;
                    if (r0 < M) {
                        Cf[(size_t)r0 * ldc + c]     = acc[mi][ni][0];
                        Cf[(size_t)r0 * ldc + c + 1] = acc[mi][ni][1];
                    }
                    if (r1 < M) {
                        Cf[(size_t)r1 * ldc + c]     = acc[mi][ni][2];
                        Cf[(size_t)r1 * ldc + c + 1] = acc[mi][ni][3];
                    }
                }
            }
        }
}

// ------- edge message + scatter (warp per edge), fp16 A gather -------------
__global__ __launch_bounds__(256) void k_edge1(const float* __restrict__ ea, const int* __restrict__ eidx) {
    int w = (blockIdx.x * blockDim.x + threadIdx.x) >> 5;
    int lane = threadIdx.x & 31;
    if (w >= Ee) return;
    int s = eidx[w], d = eidx[Ee + w];
    float c = (lane < 16) ? ea[w * 16 + lane] : 1.f;
    const __half* Ar = g_Ah + (size_t)s * W1C;
    float acc = 0.f;
#pragma unroll
    for (int dd = 0; dd < 17; dd++) {
        float cd = __shfl_sync(0xffffffffu, c, dd);
        acc += cd * __half2float(Ar[dd * 32 + lane]);
    }
    atomicAdd(&g_agg1[d * 32 + lane], acc);
}

__global__ __launch_bounds__(256) void k_edge2(const float* __restrict__ ea, const int* __restrict__ eidx) {
    int w = (blockIdx.x * blockDim.x + threadIdx.x) >> 5;
    int lane = threadIdx.x & 31;
    if (w >= Ee) return;
    int s = eidx[w], d = eidx[Ee + w];
    float c = (lane < 16) ? ea[w * 16 + lane] : 1.f;
    const __half* Ar = g_Ah + (size_t)s * W2C;
    float a0 = 0.f, a1 = 0.f;
#pragma unroll
    for (int dd = 0; dd < 17; dd++) {
        float cd = __shfl_sync(0xffffffffu, c, dd);
        __half2 h2 = *(const __half2*)&Ar[dd * 64 + 2 * lane];
        float2 f2 = __half22float2(h2);
        a0 += cd * f2.x;
        a1 += cd * f2.y;
    }
    atomicAdd(&g_agg2[d * 64 + 2 * lane],     a0);
    atomicAdd(&g_agg2[d * 64 + 2 * lane + 1], a1);
}

// ------- node updates (root term precomputed in GEMM cols) -----------------
__global__ __launch_bounds__(256) void k_update1(const float* __restrict__ bias) {
    int idx = blockIdx.x * blockDim.x + threadIdx.x;
    if (idx >= Nn * 32) return;
    int w = idx >> 5, lane = idx & 31;
    float v = g_agg1[idx] + __half2float(g_Ah[(size_t)w * W1C + 544 + lane]) + bias[lane];
    g_h1h[idx] = __float2half(fmaxf(v, 0.f));
}

__global__ __launch_bounds__(256) void k_update2(const float* __restrict__ bias,
                                                 const float* __restrict__ Wa,
                                                 const float* __restrict__ ba) {
    int w = (blockIdx.x * blockDim.x + threadIdx.x) >> 5;
    int lane = threadIdx.x & 31;
    if (w >= Nn) return;
    const __half* xr = g_Ah + (size_t)w * W2C + 1088;
    float a0 = g_agg2[w * 64 + lane] + __half2float(xr[lane]) + bias[lane];
    float a1 = g_agg2[w * 64 + 32 + lane] + __half2float(xr[32 + lane]) + bias[32 + lane];
    a0 = fmaxf(a0, 0.f);
    a1 = fmaxf(a1, 0.f);
    g_h2[w * 64 + lane] = a0;
    g_h2[w * 64 + 32 + lane] = a1;
    float sc = a0 * Wa[lane] + a1 * Wa[32 + lane];
#pragma unroll
    for (int o = 16; o; o >>= 1) sc += __shfl_xor_sync(0xffffffffu, sc, o);
    if (lane == 0) g_score[w] = sc + ba[0];
}

// ------- per-graph attention readout (scores precomputed) -> haa16 ---------
__global__ __launch_bounds__(256) void k_readout(const float* __restrict__ aaf,
                                                 const int* __restrict__ lbl) {
    __shared__ float ssc[NPG];
    __shared__ float red[8];
    __shared__ float saa[Mm * 64];
    int b = blockIdx.x, tid = threadIdx.x;
    int wid = tid >> 5, lane = tid & 31;
    for (int i = tid; i < Mm * 64; i += 256) saa[i] = 0.f;
    const float* h = g_h2 + (size_t)b * NPG * 64;
    float lmax = -1e30f;
    for (int i = tid; i < NPG; i += 256) {
        float s = g_score[b * NPG + i];
        ssc[i] = s;
        lmax = fmaxf(lmax, s);
    }
#pragma unroll
    for (int o = 16; o; o >>= 1) lmax = fmaxf(lmax, __shfl_xor_sync(0xffffffffu, lmax, o));
    if (lane == 0) red[wid] = lmax;
    __syncthreads();
    float gmax = red[0];
#pragma unroll
    for (int i = 1; i < 8; i++) gmax = fmaxf(gmax, red[i]);
    float lsum = 0.f;
    for (int i = tid; i < NPG; i += 256) {
        float e = __expf(ssc[i] - gmax);
        ssc[i] = e;
        lsum += e;
    }
#pragma unroll
    for (int o = 16; o; o >>= 1) lsum += __shfl_xor_sync(0xffffffffu, lsum, o);
    __syncthreads();
    if (lane == 0) red[wid] = lsum;
    __syncthreads();
    float gsum = 0.f;
#pragma unroll
    for (int i = 0; i < 8; i++) gsum += red[i];
    float inv = 1.f / gsum;
    for (int i = wid; i < NPG; i += 8) {
        float a = ssc[i] * inv;
        int m = lbl[b * NPG + i];
        atomicAdd(&saa[m * 64 + lane], h[i * 64 + lane] * a);
        atomicAdd(&saa[m * 64 + 32 + lane], h[i * 64 + 32 + lane] * a);
    }
    __syncthreads();
    for (int i = tid; i < Mm * KRC; i += 256) {
        int m = i / KRC, f = i - m * KRC;
        float v = 0.f;
        if (f < 64) v = saa[m * 64 + f];
        else if (f < 159) v = aaf[(b * Mm + m) * 95 + (f - 64)];
        g_haa16[(b * Mm + m) * KRC + f] = __float2half(v);
    }
}

// ------- ARMA recurrence; rootc precomputed in g_rc ------------------------
#define ARMA_SP   0
#define ARMA_SB   2800
#define ARMA_SB2  (2800 + 7168)
#define ARMA_SW   (2800 + 7168 + 7168)
#define ARMA_SMEM ((2800 + 7168 + 7168 + 16384) * 4)

__device__ __forceinline__ void arma_acc2(const float* __restrict__ Am, int lda,
                                          const float* __restrict__ Bm, int inner,
                                          ull acc[7][2], int ty, int tx) {
    for (int i = 0; i < inner; i++) {
        ull bb0 = *(const ull*)&Bm[i * 128 + 2 * tx];
        ull bb1 = *(const ull*)&Bm[i * 128 + 64 + 2 * tx];
#pragma unroll
        for (int rr = 0; rr < 7; rr++) {
            float a = Am[(ty * 7 + rr) * lda + i];
            ull aa = pack2(a, a);
            ffma2(acc[rr][0], aa, bb0);
            ffma2(acc[rr][1], aa, bb1);
        }
    }
}

__global__ __launch_bounds__(256) void k_arma2(const float* __restrict__ aw,
                                               const float* __restrict__ ab) {
    extern __shared__ float dyn[];
    float* sP  = dyn + ARMA_SP;
    float* sB  = dyn + ARMA_SB;
    float* sB2 = dyn + ARMA_SB2;
    float* sW  = dyn + ARMA_SW;
    int b = blockIdx.x / 3, k = blockIdx.x % 3;
    int tid = threadIdx.x, ty = tid >> 5, tx = tid & 31;

    for (int i = tid; i < 2800; i += 256) sP[i] = (i < 2500) ? g_P[i] : 0.f;
    for (int i = tid; i < 56 * 128; i += 256) {
        int r = i >> 7, c = i & 127;
        sB[i]  = (r < 50) ? g_rc[(size_t)(b * 50 + r) * WCOL + k * 128 + c] : 0.f;
        sB2[i] = 0.f;
    }
    __syncthreads();

    ull acc[7][2];
    for (int t = 0; t < 6; t++) {
        const float* cur = sB;
        if (t > 0) {
            const float* W = aw + (size_t)((t - 1) * 3 + k) * 16384;
            for (int i = tid * 4; i < 16384; i += 1024)
                *(float4*)&sW[i] = *(const float4*)&W[i];
            __syncthreads();
#pragma unroll
            for (int rr = 0; rr < 7; rr++) { acc[rr][0] = 0ull; acc[rr][1] = 0ull; }
            arma_acc2(sB, 128, sW, 128, acc, ty, tx);
            __syncthreads();
#pragma unroll
            for (int rr = 0; rr < 7; rr++) {
                int r = ty * 7 + rr;
                if (r < Mm) {
                    float l0, h0, l1, h1;
                    unpack2(acc[rr][0], l0, h0);
                    unpack2(acc[rr][1], l1, h1);
                    sB2[r * 128 + 2 * tx]      = l0;
                    sB2[r * 128 + 2 * tx + 1]  = h0;
                    sB2[r * 128 + 64 + 2 * tx] = l1;
                    sB2[r * 128 + 65 + 2 * tx] = h1;
                }
            }
            __syncthreads();
            cur = sB2;
        }
#pragma unroll
        for (int rr = 0; rr < 7; rr++) { acc[rr][0] = 0ull; acc[rr][1] = 0ull; }
        arma_acc2(sP, 50, cur, 50, acc, ty, tx);
        const float* bias = ab + (t * 3 + k) * 128;
        float bl0 = bias[2 * tx], bh0 = bias[2 * tx + 1];
        float bl1 = bias[64 + 2 * tx], bh1 = bias[65 + 2 * tx];
        __syncthreads();
#pragma unroll
        for (int rr = 0; rr < 7; rr++) {
            int r = ty * 7 + rr;
            if (r < Mm) {
                const float* rc = &g_rc[(size_t)(b * 50 + r) * WCOL + 384 + (t * 3 + k) * 128];
                float l0, h0, l1, h1;
                unpack2(acc[rr][0], l0, h0);
                unpack2(acc[rr][1], l1, h1);
                sB[r * 128 + 2 * tx]      = fmaxf(l0 + rc[2 * tx]      + bl0, 0.f);
                sB[r * 128 + 2 * tx + 1]  = fmaxf(h0 + rc[2 * tx + 1]  + bh0, 0.f);
                sB[r * 128 + 64 + 2 * tx] = fmaxf(l1 + rc[64 + 2 * tx] + bl1, 0.f);
                sB[r * 128 + 65 + 2 * tx] = fmaxf(h1 + rc[65 + 2 * tx] + bh1, 0.f);
            }
        }
        __syncthreads();
    }
    float* dst = g_gout + (size_t)(k * Bb + b) * Mm * 128;
    for (int i = tid; i < Mm * 128; i += 256) dst[i] = sB[i];
}

// ------- amino attention + MLP head ----------------------------------------
__global__ __launch_bounds__(128) void k_head(const float* __restrict__ Waa, const float* __restrict__ baa,
                                              const float* __restrict__ W1, const float* __restrict__ b1,
                                              const float* __restrict__ W2, const float* __restrict__ b2,
                                              const float* __restrict__ W3, const float* __restrict__ b3,
                                              const float* __restrict__ W4, const float* __restrict__ b4,
                                              float* __restrict__ out) {
    __shared__ float gv[Mm * 128];
    __shared__ float s[Mm];
    __shared__ float p[128];
    __shared__ float h1[64], h2s[32], h3[16];
    int b = blockIdx.x, tid = threadIdx.x;
    for (int i = tid; i < Mm * 128; i += 128)
        gv[i] = (g_gout[(size_t)(0 * Bb + b) * Mm * 128 + i] +
                 g_gout[(size_t)(1 * Bb + b) * Mm * 128 + i] +
                 g_gout[(size_t)(2 * Bb + b) * Mm * 128 + i]) * (1.f / 3.f);
    __syncthreads();
    if (tid < Mm) {
        float sc = baa[0];
#pragma unroll 8
        for (int c = 0; c < 128; c++) sc += gv[tid * 128 + c] * Waa[c];
        s[tid] = sc;
    }
    __syncthreads();
    if (tid == 0) {
        float mx = -1e30f;
        for (int m = 0; m < Mm; m++) mx = fmaxf(mx, s[m]);
        float sum = 0.f;
        for (int m = 0; m < Mm; m++) { s[m] = __expf(s[m] - mx); sum += s[m]; }
        float inv = 1.f / sum;
        for (int m = 0; m < Mm; m++) s[m] *= inv;
    }
    __syncthreads();
    {
        float acc = 0.f;
        for (int m = 0; m < Mm; m++) acc += gv[m * 128 + tid] * s[m];
        p[tid] = acc;
    }
    __syncthreads();
    if (tid < 64) {
        float a = b1[tid];
        for (int c = 0; c < 128; c++) a += p[c] * W1[c * 64 + tid];
        h1[tid] = fmaxf(a, 0.f);
    }
    __syncthreads();
    if (tid < 32) {
        float a = b2[tid];
        for (int c = 0; c < 64; c++) a += h1[c] * W2[c * 32 + tid];
        h2s[tid] = fmaxf(a, 0.f);
    }
    __syncthreads();
    if (tid < 16) {
        float a = b3[tid];
        for (int c = 0; c < 32; c++) a += h2s[c] * W3[c * 16 + tid];
        h3[tid] = fmaxf(a, 0.f);
    }
    __syncthreads();
    if (tid == 0) {
        float a = b4[0];
        for (int c = 0; c < 16; c++) a += h3[c] * W4[c];
        out[b] = a;
    }
}

// ---------------------------------------------------------------------------
extern "C" void kernel_launch(void* const* d_in, const int* in_sizes, int n_in,
                              void* d_out, int out_size) {
    const float* x        = (const float*)d_in[0];
    const float* ea       = (const float*)d_in[1];
    const float* aaf      = (const float*)d_in[2];
    const int*   eidx     = (const int*)d_in[3];
    const int*   lbl      = (const int*)d_in[4];
    const int*   aei      = (const int*)d_in[5];
    const float* We1      = (const float*)d_in[6];
    const float* be1      = (const float*)d_in[7];
    const float* root1    = (const float*)d_in[8];
    const float* bias1    = (const float*)d_in[9];
    const float* We2      = (const float*)d_in[10];
    const float* be2      = (const float*)d_in[11];
    const float* root2    = (const float*)d_in[12];
    const float* bias2    = (const float*)d_in[13];
    const float* WaAtom   = (const float*)d_in[14];
    const float* baAtom   = (const float*)d_in[15];
    const float* armaInit = (const float*)d_in[16];
    const float* armaW    = (const float*)d_in[17];
    const float* armaRoot = (const float*)d_in[18];
    const float* armaBias = (const float*)d_in[19];
    const float* WaAa     = (const float*)d_in[20];
    const float* baAa     = (const float*)d_in[21];
    const float* W1 = (const float*)d_in[22]; const float* b1 = (const float*)d_in[23];
    const float* W2 = (const float*)d_in[24]; const float* b2 = (const float*)d_in[25];
    const float* W3 = (const float*)d_in[26]; const float* b3 = (const float*)d_in[27];
    const float* W4 = (const float*)d_in[28]; const float* b4 = (const float*)d_in[29];
    float* out = (float*)d_out;

    void *pAh, *pX16, *pH1h, *pWt1h, *pWt2h, *pHaa16, *pWcat16;
    float* pRc;
    cudaGetSymbolAddress(&pAh,     g_Ah);
    cudaGetSymbolAddress(&pX16,    g_x16);
    cudaGetSymbolAddress(&pH1h,    g_h1h);
    cudaGetSymbolAddress(&pWt1h,   g_Wt1h);
    cudaGetSymbolAddress(&pWt2h,   g_Wt2h);
    cudaGetSymbolAddress(&pHaa16,  g_haa16);
    cudaGetSymbolAddress(&pWcat16, g_Wcat16);
    cudaGetSymbolAddress((void**)&pRc, g_rc);
    cudaFuncSetAttribute(k_arma2, cudaFuncAttributeMaxDynamicSharedMemorySize, ARMA_SMEM);
    cudaFuncSetAttribute(k_mma_res, cudaFuncAttributeMaxDynamicSharedMemorySize, 85000);

    // smem: layer1 32*584*2 + 10240 = 47616 ; layer2 32*1160*2 + 10240 = 84480
    // #1 fused prep (weights+root cols + x16 + Wcat + zeros + P)
    k_prepF<<<1024, 256>>>(x, We1, be1, root1, We2, be2, root2, armaInit, armaRoot, aei);
    // #2 layer1 GEMM (B-resident, 576 cols incl. root term)
    k_mma_res<<<391, 256, 47616>>>((const __half*)pX16, (const __half*)pWt1h,
                                   (__half*)pAh, Nn, W1C, 9, 584);
    // #3 edge1
    k_edge1<<<12500, 256>>>(ea, eidx);
    // #4 update1 (elementwise)  <- profiled slot
    k_update1<<<6250, 256>>>(bias1);
    // #5 layer2 GEMM (B-resident, 1152 cols incl. root term)
    k_mma_res<<<391, 256, 84480>>>((const __half*)pH1h, (const __half*)pWt2h,
                                   (__half*)pAh, Nn, W2C, 18, 1160);
    // #6-#7 edge2 + update2(+score)
    k_edge2<<<12500, 256>>>(ea, eidx);
    k_update2<<<6250, 256>>>(bias2, WaAtom, baAtom);
    // #8 readout (uses precomputed scores)
    k_readout<<<Bb, 256>>>(aaf, lbl);
    // #9 rc GEMM
    k_mma<<<dim3(42, 20), 256>>>((const __half*)pHaa16, (const __half*)pWcat16, pRc,
                                 Bb * Mm, WCOL, KRC, KRC, WCOL, WCOL, 0);
    // #10-#11 ARMA + head
    k_arma2<<<3 * Bb, 256, ARMA_SMEM>>>(armaW, armaBias);
    k_head<<<Bb, 128>>>(WaAa, baAa, W1, b1, W2, b2, W3, b3, W4, b4, out);
}